// round 2
// baseline (speedup 1.0000x reference)
#include <cuda_runtime.h>

// SGDW: out = p * (1 - LR*WD) - LR * (MOM * v + g)
// LR=0.01, MOM=0.9, WD=0.0001  ->  decay = 1 - 1e-6

#define LR    0.01f
#define MOM   0.9f
#define DECAY (1.0f - 0.01f * 0.0001f)

__global__ void sgdw_kernel(const float4* __restrict__ p,
                            const float4* __restrict__ g,
                            const float4* __restrict__ v,
                            float4* __restrict__ out,
                            int n4)
{
    int i = blockIdx.x * blockDim.x + threadIdx.x;
    if (i >= n4) return;

    float4 pv = p[i];
    float4 gv = g[i];
    float4 vv = v[i];

    float4 o;
    o.x = fmaf(pv.x, DECAY, -LR * fmaf(MOM, vv.x, gv.x));
    o.y = fmaf(pv.y, DECAY, -LR * fmaf(MOM, vv.y, gv.y));
    o.z = fmaf(pv.z, DECAY, -LR * fmaf(MOM, vv.z, gv.z));
    o.w = fmaf(pv.w, DECAY, -LR * fmaf(MOM, vv.w, gv.w));
    out[i] = o;
}

extern "C" void kernel_launch(void* const* d_in, const int* in_sizes, int n_in,
                              void* d_out, int out_size)
{
    float* out = (float*)d_out;

    // setup_inputs() inserts p{i}, g{i}, v{i} per tensor -> interleaved order.
    // Detect at runtime to be safe: interleaved iff first three sizes are equal
    // (p0/g0/v0 share shape (50257,1024); grouped order would give
    //  in_sizes[1] = 4096*1024 != in_sizes[0]).
    bool interleaved = (in_sizes[0] == in_sizes[1]) && (in_sizes[1] == in_sizes[2]);

    long long offset = 0;
    for (int t = 0; t < 4; t++) {
        const float* p; const float* g; const float* v; int n;
        if (interleaved) {
            p = (const float*)d_in[3 * t + 0];
            g = (const float*)d_in[3 * t + 1];
            v = (const float*)d_in[3 * t + 2];
            n = in_sizes[3 * t];
        } else {
            p = (const float*)d_in[t];
            g = (const float*)d_in[4 + t];
            v = (const float*)d_in[8 + t];
            n = in_sizes[t];
        }

        int n4 = n / 4;   // all element counts divisible by 1024
        int threads = 256;
        int blocks = (n4 + threads - 1) / threads;
        sgdw_kernel<<<blocks, threads>>>((const float4*)p,
                                         (const float4*)g,
                                         (const float4*)v,
                                         (float4*)(out + offset),
                                         n4);
        offset += n;
    }
}